// round 12
// baseline (speedup 1.0000x reference)
#include <cuda_runtime.h>
#include <cuda_bf16.h>
#include <cuda_fp16.h>

// ---------------------------------------------------------------------------
// Net_67765993996461  R12: single-sync-per-tap conv pipeline, B double-buffered,
// vectorized fp16 B fill (STS.128), fp16 spike buffers. 2-way fp16 weight split
// (pre-scaled 2^10). 64KB smem -> 3 CTAs/SM.
// ---------------------------------------------------------------------------

#define TAUF ((float)(10.0 / 7.0))

constexpr int BB   = 32;
constexpr int CC   = 64;
constexpr int TT_  = 129;
constexpr int TIN  = 128;
constexpr int MM   = 40;
constexpr int N_SP = TT_ * MM;        // 5160
constexpr int LANES = BB * CC * MM;   // 81920
constexpr int VOL   = BB * CC * N_SP;

// conv smem: A = 2 x (128 rows x 128B), B = 2 x (64 rows x 256B), all swizzled
constexpr int A_TILE = 128 * 128;              // 16384
constexpr int B_TILE = 64 * 256;               // 16384
constexpr int B_OFF  = 2 * A_TILE;             // 32768
constexpr int SMEM_BYTES = B_OFF + 2 * B_TILE; // 65536 -> 3 CTAs/SM (192KB)

constexpr float WSCALE   = 1024.0f;            // 2^10
constexpr float WUNSCALE = 1.0f / 1024.0f;     // 2^-10 (exact)

// Scratch
__device__ __half g_s1[VOL];
__device__ float  g_u [VOL];
__device__ __half g_s2[VOL];
__device__ __half g_w2s[12 * 2 * CC * CC];     // [tap][split][co][ci]
__device__ __half g_w3s[12 * 2 * CC * CC];
__device__ float  g_ssum[BB * CC * MM];

// ---------------------------------------------------------------------------
// conv1 + LIF: thread per (b,c,m), 4x3 register window, 3 LDG per t-step.
// ---------------------------------------------------------------------------
__global__ void conv1_lif_kernel(const float* __restrict__ x,
                                 const float* __restrict__ w1) {
    int idx = blockIdx.x * blockDim.x + threadIdx.x;
    if (idx >= LANES) return;
    int m = idx % MM;
    int c = (idx / MM) % CC;
    int b = idx / (MM * CC);

    float w[12];
#pragma unroll
    for (int k = 0; k < 12; k++) w[k] = w1[c * 12 + k];

    const float* xb = x + (size_t)b * TIN * MM;

    float a0[3], a1[3], a2[3], a3[3];
    auto load_row = [&](float* d, int t) {
        if (t >= 0 && t < TIN) {
            const float* r = xb + t * MM;
            d[0] = (m > 0)      ? r[m - 1] : 0.f;
            d[1] = r[m];
            d[2] = (m < MM - 1) ? r[m + 1] : 0.f;
        } else {
            d[0] = d[1] = d[2] = 0.f;
        }
    };
#pragma unroll
    for (int j = 0; j < 3; j++) { a0[j] = 0.f; a1[j] = 0.f; }
    load_row(a2, 0);
    load_row(a3, 1);

    __half* sp = g_s1 + (size_t)(b * CC + c) * N_SP + m;
    float v = 0.f;
    for (int t = 0; t < TT_; t++) {
        float u = 0.f;
#pragma unroll
        for (int j = 0; j < 3; j++) {
            u += w[0 + j] * a0[j];
            u += w[3 + j] * a1[j];
            u += w[6 + j] * a2[j];
            u += w[9 + j] * a3[j];
        }
        v = v + (u - v) / TAUF;
        float s = (v >= 1.f) ? 1.f : 0.f;
        sp[t * MM] = __float2half_rn(s);
        v = (v >= 1.f) ? 0.f : v;
#pragma unroll
        for (int j = 0; j < 3; j++) { a0[j] = a1[j]; a1[j] = a2[j]; a2[j] = a3[j]; }
        load_row(a3, t + 2);
    }
}

// ---------------------------------------------------------------------------
// 2-way fp16 split (RZ), weights pre-scaled by 2^10. Layout [tap][split][co][ci].
// ---------------------------------------------------------------------------
__global__ void wsplit_kernel(const float* __restrict__ wa,
                              const float* __restrict__ wb) {
    int which = blockIdx.y;
    const float* w = which ? wb : wa;
    __half* ws = which ? g_w3s : g_w2s;
    int i = blockIdx.x * blockDim.x + threadIdx.x;   // i = co*768 + ci*12 + tap
    if (i >= CC * CC * 12) return;
    int co  = i / 768;
    int r   = i - co * 768;
    int ci  = r / 12;
    int tap = r - ci * 12;
    float v = w[i] * WSCALE;
    __half h0 = __float2half_rz(v);
    float r1 = v - __half2float(h0);          // exact in fp32
    __half h1 = __float2half_rz(r1);
    ws[((tap * 2 + 0) * CC + co) * CC + ci] = h0;
    ws[((tap * 2 + 1) * CC + co) * CC + ci] = h1;
}

// ---------------------------------------------------------------------------
__device__ __forceinline__ void mma16816(float* d, const unsigned* a, const unsigned* b) {
    asm volatile(
        "mma.sync.aligned.m16n8k16.row.col.f32.f16.f16.f32 "
        "{%0,%1,%2,%3}, {%4,%5,%6,%7}, {%8,%9}, {%0,%1,%2,%3};\n"
        : "+f"(d[0]), "+f"(d[1]), "+f"(d[2]), "+f"(d[3])
        : "r"(a[0]), "r"(a[1]), "r"(a[2]), "r"(a[3]), "r"(b[0]), "r"(b[1]));
}
__device__ __forceinline__ void ldsm_x4(unsigned addr, unsigned& r0, unsigned& r1,
                                        unsigned& r2, unsigned& r3) {
    asm volatile("ldmatrix.sync.aligned.m8n8.x4.shared.b16 {%0,%1,%2,%3}, [%4];\n"
                 : "=r"(r0), "=r"(r1), "=r"(r2), "=r"(r3) : "r"(addr));
}
__device__ __forceinline__ void ldsm_x4_t(unsigned addr, unsigned& r0, unsigned& r1,
                                          unsigned& r2, unsigned& r3) {
    asm volatile("ldmatrix.sync.aligned.m8n8.x4.trans.shared.b16 {%0,%1,%2,%3}, [%4];\n"
                 : "=r"(r0), "=r"(r1), "=r"(r2), "=r"(r3) : "r"(addr));
}
__device__ __forceinline__ unsigned smem_u32(const void* p) {
    return (unsigned)__cvta_generic_to_shared(p);
}
__device__ __forceinline__ void cp_async16(unsigned dst, const void* src) {
    asm volatile("cp.async.cg.shared.global [%0], [%1], 16;\n"
                 :: "r"(dst), "l"(src) : "memory");
}
#define CP_COMMIT() asm volatile("cp.async.commit_group;\n" ::: "memory")
#define CP_WAIT0()  asm volatile("cp.async.wait_group 0;\n" ::: "memory")

// ---------------------------------------------------------------------------
// Conv GEMM: 64co x 128n per CTA, 8 warps (32co x 32n), tap-decomposed.
// A: 2 x (128 rows x 128B), cp.async double-buffered.
// B: 2 x (64 ci x 256B), SIMT double-buffered (vectorized STS.128 fill).
// ONE __syncthreads per tap; fills of tap+1 overlap mma of tap.
// ---------------------------------------------------------------------------
template <int LAYER, int DT, int PT, int DM, int PM>
__global__ __launch_bounds__(256, 3) void conv_mma_kernel() {
    extern __shared__ __align__(128) char sm[];
    unsigned sbase = smem_u32(sm);
    unsigned Ab0 = sbase;
    unsigned Ab1 = sbase + A_TILE;
    unsigned Bb0 = sbase + B_OFF;
    unsigned Bb1 = sbase + B_OFF + B_TILE;

    const __half* __restrict__ in = (LAYER == 2) ? g_s1 : g_s2;
    const __half* __restrict__ ws = (LAYER == 2) ? g_w2s : g_w3s;

    int b  = blockIdx.y;
    int n0 = blockIdx.x * 128;
    int tid  = threadIdx.x;
    int warp = tid >> 5, lane = tid & 31;
    int wco = (warp >> 2) * 32;
    int wn  = (warp & 3) * 32;

    const __half* inb = in + (size_t)b * CC * N_SP;

    float acc[2][4][4];
#pragma unroll
    for (int i = 0; i < 2; i++)
#pragma unroll
        for (int j = 0; j < 4; j++)
#pragma unroll
            for (int q = 0; q < 4; q++) acc[i][j][q] = 0.f;

    // A fill: 1024 uint4 per tap (2 splits x 64 rows x 128B), cp.async
    auto fillA = [&](int tap, unsigned Ad) {
        const uint4* wsrc = (const uint4*)(ws + (size_t)tap * 2 * CC * CC);
#pragma unroll
        for (int r = 0; r < 4; r++) {
            int i = tid + r * 256;
            int row = i >> 3, q = i & 7;
            unsigned dst = Ad + row * 128 + ((q ^ (row & 7)) << 4);
            cp_async16(dst, wsrc + i);
        }
        CP_COMMIT();
    };

    // B fill (vectorized): unit = (ci, g): 8 n at n0+g*8 (never crosses a t-row
    // since 40 % 8 == 0), 8 predicated LDG.16 -> pack -> 1 STS.128 (swizzled).
    // Thread handles g = tid&15, ci = (tid>>4) + 16r.
    int g_  = tid & 15;
    int cib = tid >> 4;
    int nst = n0 + g_ * 8;
    int trow = nst / MM;
    int mrow = nst - trow * MM;
    auto fillB = [&](int tap, char* Bpd) {
        int kt = tap / 3, km = tap - kt * 3;
        int tt = trow + DT * kt - PT;
        int mmb = mrow + DM * km - PM;
        bool tv = (tt >= 0) & (tt < TT_);
        const __half* srow = inb + tt * MM + mmb;
        unsigned short h[8];
#pragma unroll
        for (int r = 0; r < 4; r++) {
            int ci = cib + r * 16;
            const unsigned short* src = (const unsigned short*)(srow + (size_t)ci * N_SP);
#pragma unroll
            for (int j = 0; j < 8; j++) {
                int mm = mmb + j;
                bool ok = tv & (mm >= 0) & (mm < MM);
                h[j] = ok ? src[j] : (unsigned short)0;
            }
            uint4 pk;
            pk.x = (unsigned)h[0] | ((unsigned)h[1] << 16);
            pk.y = (unsigned)h[2] | ((unsigned)h[3] << 16);
            pk.z = (unsigned)h[4] | ((unsigned)h[5] << 16);
            pk.w = (unsigned)h[6] | ((unsigned)h[7] << 16);
            *(uint4*)(Bpd + ci * 256 + ((g_ ^ (ci & 7)) << 4)) = pk;
        }
    };

    auto domma = [&](unsigned Ad, unsigned Bd) {
#pragma unroll
        for (int ks = 0; ks < 4; ks++) {
            unsigned bf[4][2];
#pragma unroll
            for (int g = 0; g < 2; g++) {
                int ci = ks * 16 + (lane & 15);
                int nseg = (wn >> 3) + g * 2 + (lane >> 4);
                unsigned addr = Bd + ci * 256 + (((unsigned)(nseg ^ (ci & 7))) << 4);
                unsigned q0, q1, q2, q3;
                ldsm_x4_t(addr, q0, q1, q2, q3);
                bf[2 * g][0] = q0; bf[2 * g][1] = q1;
                bf[2 * g + 1][0] = q2; bf[2 * g + 1][1] = q3;
            }
#pragma unroll
            for (int s = 0; s < 2; s++) {
#pragma unroll
                for (int mf = 0; mf < 2; mf++) {
                    int row = s * 64 + wco + mf * 16 + (lane & 15);
                    int j = ks * 2 + (lane >> 4);
                    unsigned addr = Ad + row * 128 + (((unsigned)(j ^ (row & 7))) << 4);
                    unsigned a[4];
                    ldsm_x4(addr, a[0], a[1], a[2], a[3]);
#pragma unroll
                    for (int nf = 0; nf < 4; nf++)
                        mma16816(acc[mf][nf], a, bf[nf]);
                }
            }
        }
    };

    // Pipeline: one sync per tap; fills of tap+1 overlap mma of tap.
    fillA(0, Ab0);
    fillB(0, sm + B_OFF);
#pragma unroll 1
    for (int tap = 0; tap < 12; tap++) {
        CP_WAIT0();          // A(tap) complete (issued one iteration earlier)
        __syncthreads();     // B(tap) visible; prior mma reads of reused bufs done
        if (tap < 11) {
            fillA(tap + 1, (tap & 1) ? Ab0 : Ab1);
            fillB(tap + 1, sm + B_OFF + (((tap + 1) & 1) ? B_TILE : 0));
        }
        domma((tap & 1) ? Ab1 : Ab0, (tap & 1) ? Bb1 : Bb0);
    }

    int lrow = lane >> 2, lk = (lane & 3) * 2;
    float* outb = g_u + (size_t)b * CC * N_SP;
#pragma unroll
    for (int mf = 0; mf < 2; mf++) {
#pragma unroll
        for (int nf = 0; nf < 4; nf++) {
            int co = wco + mf * 16 + lrow;
            int n  = n0 + wn + nf * 8 + lk;
            float* p1 = outb + (size_t)co * N_SP + n;
            float* p2 = outb + (size_t)(co + 8) * N_SP + n;
            if (n + 1 < N_SP) {
                *(float2*)p1 = make_float2(acc[mf][nf][0] * WUNSCALE,
                                           acc[mf][nf][1] * WUNSCALE);
                *(float2*)p2 = make_float2(acc[mf][nf][2] * WUNSCALE,
                                           acc[mf][nf][3] * WUNSCALE);
            } else if (n < N_SP) {
                p1[0] = acc[mf][nf][0] * WUNSCALE;
                p2[0] = acc[mf][nf][2] * WUNSCALE;
            }
        }
    }
}

// ---------------------------------------------------------------------------
// LIF over t with MLP=8 load batching. Writes fp16 spikes to g_s2.
// ---------------------------------------------------------------------------
__global__ void lif2_kernel() {
    int idx = blockIdx.x * blockDim.x + threadIdx.x;
    if (idx >= LANES) return;
    int m = idx % MM;
    int bc = idx / MM;
    const float* up = g_u + (size_t)bc * N_SP + m;
    __half* sp = g_s2 + (size_t)bc * N_SP + m;
    float v = 0.f;
#pragma unroll 1
    for (int t = 0; t < 128; t += 8) {
        float xr[8];
#pragma unroll
        for (int j = 0; j < 8; j++) xr[j] = up[(t + j) * MM];
        __half sr[8];
#pragma unroll
        for (int j = 0; j < 8; j++) {
            v = v + (xr[j] - v) / TAUF;
            sr[j] = __float2half_rn((v >= 1.f) ? 1.f : 0.f);
            v = (v >= 1.f) ? 0.f : v;
        }
#pragma unroll
        for (int j = 0; j < 8; j++) sp[(t + j) * MM] = sr[j];
    }
    {   // t = 128
        float x0 = up[128 * MM];
        v = v + (x0 - v) / TAUF;
        sp[128 * MM] = __float2half_rn((v >= 1.f) ? 1.f : 0.f);
    }
}

// ---------------------------------------------------------------------------
// LIF3 fused with time-sum (MLP=8): writes g_ssum directly.
// ---------------------------------------------------------------------------
__global__ void lif3_tsum_kernel() {
    int idx = blockIdx.x * blockDim.x + threadIdx.x;
    if (idx >= LANES) return;
    int m = idx % MM;
    int bc = idx / MM;
    const float* up = g_u + (size_t)bc * N_SP + m;
    float v = 0.f, a = 0.f;
#pragma unroll 1
    for (int t = 0; t < 128; t += 8) {
        float xr[8];
#pragma unroll
        for (int j = 0; j < 8; j++) xr[j] = up[(t + j) * MM];
#pragma unroll
        for (int j = 0; j < 8; j++) {
            v = v + (xr[j] - v) / TAUF;
            if (v >= 1.f) { a += 1.f; v = 0.f; }
        }
    }
    {
        float x0 = up[128 * MM];
        v = v + (x0 - v) / TAUF;
        if (v >= 1.f) a += 1.f;
    }
    g_ssum[(size_t)bc * MM + m] = a;
}

// ---------------------------------------------------------------------------
__global__ void fc_kernel(const float* __restrict__ wf,
                          const float* __restrict__ bf,
                          float* __restrict__ y) {
    int b = blockIdx.x, j = blockIdx.y;
    int tid = threadIdx.x;
    const float* sb = g_ssum + b * (CC * MM);
    const float* wj = wf + j * (CC * MM);
    float acc = 0.f;
    for (int i = tid; i < CC * MM; i += 128) acc += sb[i] * wj[i];
    __shared__ float red[128];
    red[tid] = acc;
    __syncthreads();
    for (int s = 64; s > 0; s >>= 1) {
        if (tid < s) red[tid] += red[tid + s];
        __syncthreads();
    }
    if (tid == 0) y[b * 12 + j] = red[0] * (1.0f / 129.0f) + bf[j];
}

// ---------------------------------------------------------------------------
extern "C" void kernel_launch(void* const* d_in, const int* in_sizes, int n_in,
                              void* d_out, int out_size) {
    const float* x  = (const float*)d_in[0];
    const float* w1 = (const float*)d_in[1];
    const float* w2 = (const float*)d_in[2];
    const float* w3 = (const float*)d_in[3];
    const float* wf = (const float*)d_in[4];
    const float* bf = (const float*)d_in[5];
    float* y = (float*)d_out;

    static int smem_set = 0;
    if (!smem_set) {
        cudaFuncSetAttribute(conv_mma_kernel<2, 4, 6, 3, 3>,
                             cudaFuncAttributeMaxDynamicSharedMemorySize, SMEM_BYTES);
        cudaFuncSetAttribute(conv_mma_kernel<3, 16, 24, 9, 9>,
                             cudaFuncAttributeMaxDynamicSharedMemorySize, SMEM_BYTES);
        smem_set = 1;
    }

    {
        dim3 grid((CC * CC * 12 + 255) / 256, 2);
        wsplit_kernel<<<grid, 256>>>(w2, w3);
    }

    conv1_lif_kernel<<<(LANES + 255) / 256, 256>>>(x, w1);

    {
        dim3 grid((N_SP + 127) / 128, BB);
        conv_mma_kernel<2, 4, 6, 3, 3><<<grid, 256, SMEM_BYTES>>>();
    }
    lif2_kernel<<<(LANES + 255) / 256, 256>>>();

    {
        dim3 grid((N_SP + 127) / 128, BB);
        conv_mma_kernel<3, 16, 24, 9, 9><<<grid, 256, SMEM_BYTES>>>();
    }
    lif3_tsum_kernel<<<(LANES + 255) / 256, 256>>>();

    {
        dim3 grid(BB, 12);
        fc_kernel<<<grid, 128>>>(wf, bf, y);
    }
}

// round 13
// speedup vs baseline: 1.2077x; 1.2077x over previous
#include <cuda_runtime.h>
#include <cuda_bf16.h>
#include <cuda_fp16.h>

// ---------------------------------------------------------------------------
// Net_67765993996461  R13: R11 conv architecture (proven 359us) + division ->
// multiply in all LIF recurrences + fp16 spike buffers (no cvt in fillB).
// 2-way fp16 weight split (pre-scaled 2^10), 48KB smem, 3 CTAs/SM.
// ---------------------------------------------------------------------------

#define TAUF ((float)(10.0 / 7.0))
constexpr float INV_TAU = 1.0f / TAUF;         // compile-time fp32 constant

constexpr int BB   = 32;
constexpr int CC   = 64;
constexpr int TT_  = 129;
constexpr int TIN  = 128;
constexpr int MM   = 40;
constexpr int N_SP = TT_ * MM;        // 5160
constexpr int LANES = BB * CC * MM;   // 81920
constexpr int VOL   = BB * CC * N_SP;

// conv smem: A = 2 x (128 rows x 128B swizzled), B = 64 rows x 256B swizzled
constexpr int A_TILE = 128 * 128;              // 16384 per buffer
constexpr int B_OFF  = 2 * A_TILE;             // 32768
constexpr int SMEM_BYTES = B_OFF + 64 * 256;   // 49152 (48KB) -> 3 CTAs/SM

constexpr float WSCALE   = 1024.0f;            // 2^10
constexpr float WUNSCALE = 1.0f / 1024.0f;     // 2^-10 (exact)

// Scratch
__device__ __half g_s1[VOL];
__device__ float  g_u [VOL];
__device__ __half g_s2[VOL];
__device__ __half g_w2s[12 * 2 * CC * CC];     // [tap][split][co][ci]
__device__ __half g_w3s[12 * 2 * CC * CC];
__device__ float  g_ssum[BB * CC * MM];

// ---------------------------------------------------------------------------
// conv1 + LIF: thread per (b,c,m), 4x3 register window, 3 LDG per t-step.
// ---------------------------------------------------------------------------
__global__ void conv1_lif_kernel(const float* __restrict__ x,
                                 const float* __restrict__ w1) {
    int idx = blockIdx.x * blockDim.x + threadIdx.x;
    if (idx >= LANES) return;
    int m = idx % MM;
    int c = (idx / MM) % CC;
    int b = idx / (MM * CC);

    float w[12];
#pragma unroll
    for (int k = 0; k < 12; k++) w[k] = w1[c * 12 + k];

    const float* xb = x + (size_t)b * TIN * MM;

    float a0[3], a1[3], a2[3], a3[3];
    auto load_row = [&](float* d, int t) {
        if (t >= 0 && t < TIN) {
            const float* r = xb + t * MM;
            d[0] = (m > 0)      ? r[m - 1] : 0.f;
            d[1] = r[m];
            d[2] = (m < MM - 1) ? r[m + 1] : 0.f;
        } else {
            d[0] = d[1] = d[2] = 0.f;
        }
    };
#pragma unroll
    for (int j = 0; j < 3; j++) { a0[j] = 0.f; a1[j] = 0.f; }
    load_row(a2, 0);
    load_row(a3, 1);

    __half* sp = g_s1 + (size_t)(b * CC + c) * N_SP + m;
    float v = 0.f;
    for (int t = 0; t < TT_; t++) {
        float u = 0.f;
#pragma unroll
        for (int j = 0; j < 3; j++) {
            u += w[0 + j] * a0[j];
            u += w[3 + j] * a1[j];
            u += w[6 + j] * a2[j];
            u += w[9 + j] * a3[j];
        }
        v = v + (u - v) * INV_TAU;
        float s = (v >= 1.f) ? 1.f : 0.f;
        sp[t * MM] = __float2half_rn(s);
        v = (v >= 1.f) ? 0.f : v;
#pragma unroll
        for (int j = 0; j < 3; j++) { a0[j] = a1[j]; a1[j] = a2[j]; a2[j] = a3[j]; }
        load_row(a3, t + 2);
    }
}

// ---------------------------------------------------------------------------
// 2-way fp16 split (RZ), weights pre-scaled by 2^10. Layout [tap][split][co][ci].
// ---------------------------------------------------------------------------
__global__ void wsplit_kernel(const float* __restrict__ wa,
                              const float* __restrict__ wb) {
    int which = blockIdx.y;
    const float* w = which ? wb : wa;
    __half* ws = which ? g_w3s : g_w2s;
    int i = blockIdx.x * blockDim.x + threadIdx.x;   // i = co*768 + ci*12 + tap
    if (i >= CC * CC * 12) return;
    int co  = i / 768;
    int r   = i - co * 768;
    int ci  = r / 12;
    int tap = r - ci * 12;
    float v = w[i] * WSCALE;
    __half h0 = __float2half_rz(v);
    float r1 = v - __half2float(h0);          // exact in fp32
    __half h1 = __float2half_rz(r1);
    ws[((tap * 2 + 0) * CC + co) * CC + ci] = h0;
    ws[((tap * 2 + 1) * CC + co) * CC + ci] = h1;
}

// ---------------------------------------------------------------------------
__device__ __forceinline__ void mma16816(float* d, const unsigned* a, const unsigned* b) {
    asm volatile(
        "mma.sync.aligned.m16n8k16.row.col.f32.f16.f16.f32 "
        "{%0,%1,%2,%3}, {%4,%5,%6,%7}, {%8,%9}, {%0,%1,%2,%3};\n"
        : "+f"(d[0]), "+f"(d[1]), "+f"(d[2]), "+f"(d[3])
        : "r"(a[0]), "r"(a[1]), "r"(a[2]), "r"(a[3]), "r"(b[0]), "r"(b[1]));
}
__device__ __forceinline__ void ldsm_x4(unsigned addr, unsigned& r0, unsigned& r1,
                                        unsigned& r2, unsigned& r3) {
    asm volatile("ldmatrix.sync.aligned.m8n8.x4.shared.b16 {%0,%1,%2,%3}, [%4];\n"
                 : "=r"(r0), "=r"(r1), "=r"(r2), "=r"(r3) : "r"(addr));
}
__device__ __forceinline__ void ldsm_x4_t(unsigned addr, unsigned& r0, unsigned& r1,
                                          unsigned& r2, unsigned& r3) {
    asm volatile("ldmatrix.sync.aligned.m8n8.x4.trans.shared.b16 {%0,%1,%2,%3}, [%4];\n"
                 : "=r"(r0), "=r"(r1), "=r"(r2), "=r"(r3) : "r"(addr));
}
__device__ __forceinline__ unsigned smem_u32(const void* p) {
    return (unsigned)__cvta_generic_to_shared(p);
}
__device__ __forceinline__ void cp_async16(unsigned dst, const void* src) {
    asm volatile("cp.async.cg.shared.global [%0], [%1], 16;\n"
                 :: "r"(dst), "l"(src) : "memory");
}
#define CP_COMMIT() asm volatile("cp.async.commit_group;\n" ::: "memory")
#define CP_WAIT1()  asm volatile("cp.async.wait_group 1;\n" ::: "memory")
#define CP_WAIT0()  asm volatile("cp.async.wait_group 0;\n" ::: "memory")

// ---------------------------------------------------------------------------
// Conv GEMM (R11-proven): 64co x 128n per CTA, 8 warps (32co x 32n).
// A (weights, 128 rows x 128B, XOR-swizzled): double-buffered via cp.async.
// B (spikes,   64 rows x 256B, XOR-swizzled): single-buffered, fp16 copy.
// ---------------------------------------------------------------------------
template <int LAYER, int DT, int PT, int DM, int PM>
__global__ __launch_bounds__(256, 3) void conv_mma_kernel() {
    extern __shared__ __align__(128) char sm[];
    unsigned sbase = smem_u32(sm);
    unsigned Ab0 = sbase;
    unsigned Ab1 = sbase + A_TILE;
    unsigned Bb  = sbase + B_OFF;
    char* Bp = sm + B_OFF;

    const __half* __restrict__ in = (LAYER == 2) ? g_s1 : g_s2;
    const __half* __restrict__ ws = (LAYER == 2) ? g_w2s : g_w3s;

    int b  = blockIdx.y;
    int n0 = blockIdx.x * 128;
    int tid  = threadIdx.x;
    int warp = tid >> 5, lane = tid & 31;
    int wco = (warp >> 2) * 32;
    int wn  = (warp & 3) * 32;

    const __half* inb = in + (size_t)b * CC * N_SP;

    int nl   = tid & 127;
    int half = tid >> 7;
    int ng  = n0 + nl;
    int tt0 = ng / MM;
    int mm0 = ng - tt0 * MM;

    float acc[2][4][4];
#pragma unroll
    for (int i = 0; i < 2; i++)
#pragma unroll
        for (int j = 0; j < 4; j++)
#pragma unroll
            for (int q = 0; q < 4; q++) acc[i][j][q] = 0.f;

    // A fill: 1024 uint4 per tap (2 splits x 64 rows x 128B), cp.async
    auto fillA = [&](int tap, unsigned Ad) {
        const uint4* wsrc = (const uint4*)(ws + (size_t)tap * 2 * CC * CC);
#pragma unroll
        for (int r = 0; r < 4; r++) {
            int i = tid + r * 256;
            int row = i >> 3, q = i & 7;
            unsigned dst = Ad + row * 128 + ((q ^ (row & 7)) << 4);
            cp_async16(dst, wsrc + i);
        }
        CP_COMMIT();
    };

    // B fill: shifted-plane gather, fp16 direct copy (no cvt), one predicate
    auto fillB = [&](int tap) {
        int kt = tap / 3, km = tap - kt * 3;
        int tt = tt0 + DT * kt - PT;
        int mm = mm0 + DM * km - PM;
        bool p = (tt >= 0) & (tt < TT_) & (mm >= 0) & (mm < MM);
        const unsigned short* src =
            (const unsigned short*)(inb + (size_t)(half * 32) * N_SP + (tt * MM + mm));
        unsigned segsw = ((unsigned)(nl >> 3) << 4);
        unsigned inoff = ((unsigned)(nl & 7) << 1);
        if (p) {
#pragma unroll
            for (int c = 0; c < 32; c++) {
                int ci = half * 32 + c;
                unsigned off = ci * 256 + (segsw ^ ((unsigned)(ci & 7) << 4)) + inoff;
                *(unsigned short*)(Bp + off) = src[(size_t)c * N_SP];
            }
        } else {
#pragma unroll
            for (int c = 0; c < 32; c++) {
                int ci = half * 32 + c;
                unsigned off = ci * 256 + (segsw ^ ((unsigned)(ci & 7) << 4)) + inoff;
                *(unsigned short*)(Bp + off) = 0;
            }
        }
    };

    auto domma = [&](unsigned Ad) {
#pragma unroll
        for (int ks = 0; ks < 4; ks++) {
            unsigned bf[4][2];
#pragma unroll
            for (int g = 0; g < 2; g++) {
                int ci = ks * 16 + (lane & 15);
                int nseg = (wn >> 3) + g * 2 + (lane >> 4);
                unsigned addr = Bb + ci * 256 + (((unsigned)(nseg ^ (ci & 7))) << 4);
                unsigned q0, q1, q2, q3;
                ldsm_x4_t(addr, q0, q1, q2, q3);
                bf[2 * g][0] = q0; bf[2 * g][1] = q1;
                bf[2 * g + 1][0] = q2; bf[2 * g + 1][1] = q3;
            }
#pragma unroll
            for (int s = 0; s < 2; s++) {
#pragma unroll
                for (int mf = 0; mf < 2; mf++) {
                    int row = s * 64 + wco + mf * 16 + (lane & 15);
                    int j = ks * 2 + (lane >> 4);
                    unsigned addr = Ad + row * 128 + (((unsigned)(j ^ (row & 7))) << 4);
                    unsigned a[4];
                    ldsm_x4(addr, a[0], a[1], a[2], a[3]);
#pragma unroll
                    for (int nf = 0; nf < 4; nf++)
                        mma16816(acc[mf][nf], a, bf[nf]);
                }
            }
        }
    };

    fillA(0, Ab0);
#pragma unroll 1
    for (int tap = 0; tap < 12; tap++) {
        unsigned Acur = (tap & 1) ? Ab1 : Ab0;
        fillB(tap);                                   // B free: post-mma barrier passed
        if (tap < 11) {
            fillA(tap + 1, (tap & 1) ? Ab0 : Ab1);    // other A buffer
            CP_WAIT1();                               // A(tap) done, A(tap+1) in flight
        } else {
            CP_WAIT0();
        }
        __syncthreads();                              // A(tap)+B(tap) visible
        domma(Acur);
        __syncthreads();                              // B reads done -> next fillB safe
    }

    int lrow = lane >> 2, lk = (lane & 3) * 2;
    float* outb = g_u + (size_t)b * CC * N_SP;
#pragma unroll
    for (int mf = 0; mf < 2; mf++) {
#pragma unroll
        for (int nf = 0; nf < 4; nf++) {
            int co = wco + mf * 16 + lrow;
            int n  = n0 + wn + nf * 8 + lk;
            float* p1 = outb + (size_t)co * N_SP + n;
            float* p2 = outb + (size_t)(co + 8) * N_SP + n;
            if (n + 1 < N_SP) {
                *(float2*)p1 = make_float2(acc[mf][nf][0] * WUNSCALE,
                                           acc[mf][nf][1] * WUNSCALE);
                *(float2*)p2 = make_float2(acc[mf][nf][2] * WUNSCALE,
                                           acc[mf][nf][3] * WUNSCALE);
            } else if (n < N_SP) {
                p1[0] = acc[mf][nf][0] * WUNSCALE;
                p2[0] = acc[mf][nf][2] * WUNSCALE;
            }
        }
    }
}

// ---------------------------------------------------------------------------
// LIF over t with MLP=8 load batching. Writes fp16 spikes to g_s2.
// ---------------------------------------------------------------------------
__global__ void lif2_kernel() {
    int idx = blockIdx.x * blockDim.x + threadIdx.x;
    if (idx >= LANES) return;
    int m = idx % MM;
    int bc = idx / MM;
    const float* up = g_u + (size_t)bc * N_SP + m;
    __half* sp = g_s2 + (size_t)bc * N_SP + m;
    float v = 0.f;
#pragma unroll 1
    for (int t = 0; t < 128; t += 8) {
        float xr[8];
#pragma unroll
        for (int j = 0; j < 8; j++) xr[j] = up[(t + j) * MM];
        __half sr[8];
#pragma unroll
        for (int j = 0; j < 8; j++) {
            v = v + (xr[j] - v) * INV_TAU;
            sr[j] = __float2half_rn((v >= 1.f) ? 1.f : 0.f);
            v = (v >= 1.f) ? 0.f : v;
        }
#pragma unroll
        for (int j = 0; j < 8; j++) sp[(t + j) * MM] = sr[j];
    }
    {   // t = 128
        float x0 = up[128 * MM];
        v = v + (x0 - v) * INV_TAU;
        sp[128 * MM] = __float2half_rn((v >= 1.f) ? 1.f : 0.f);
    }
}

// ---------------------------------------------------------------------------
// LIF3 fused with time-sum (MLP=8): writes g_ssum directly.
// ---------------------------------------------------------------------------
__global__ void lif3_tsum_kernel() {
    int idx = blockIdx.x * blockDim.x + threadIdx.x;
    if (idx >= LANES) return;
    int m = idx % MM;
    int bc = idx / MM;
    const float* up = g_u + (size_t)bc * N_SP + m;
    float v = 0.f, a = 0.f;
#pragma unroll 1
    for (int t = 0; t < 128; t += 8) {
        float xr[8];
#pragma unroll
        for (int j = 0; j < 8; j++) xr[j] = up[(t + j) * MM];
#pragma unroll
        for (int j = 0; j < 8; j++) {
            v = v + (xr[j] - v) * INV_TAU;
            if (v >= 1.f) { a += 1.f; v = 0.f; }
        }
    }
    {
        float x0 = up[128 * MM];
        v = v + (x0 - v) * INV_TAU;
        if (v >= 1.f) a += 1.f;
    }
    g_ssum[(size_t)bc * MM + m] = a;
}

// ---------------------------------------------------------------------------
__global__ void fc_kernel(const float* __restrict__ wf,
                          const float* __restrict__ bf,
                          float* __restrict__ y) {
    int b = blockIdx.x, j = blockIdx.y;
    int tid = threadIdx.x;
    const float* sb = g_ssum + b * (CC * MM);
    const float* wj = wf + j * (CC * MM);
    float acc = 0.f;
    for (int i = tid; i < CC * MM; i += 128) acc += sb[i] * wj[i];
    __shared__ float red[128];
    red[tid] = acc;
    __syncthreads();
    for (int s = 64; s > 0; s >>= 1) {
        if (tid < s) red[tid] += red[tid + s];
        __syncthreads();
    }
    if (tid == 0) y[b * 12 + j] = red[0] * (1.0f / 129.0f) + bf[j];
}

// ---------------------------------------------------------------------------
extern "C" void kernel_launch(void* const* d_in, const int* in_sizes, int n_in,
                              void* d_out, int out_size) {
    const float* x  = (const float*)d_in[0];
    const float* w1 = (const float*)d_in[1];
    const float* w2 = (const float*)d_in[2];
    const float* w3 = (const float*)d_in[3];
    const float* wf = (const float*)d_in[4];
    const float* bf = (const float*)d_in[5];
    float* y = (float*)d_out;

    static int smem_set = 0;
    if (!smem_set) {
        cudaFuncSetAttribute(conv_mma_kernel<2, 4, 6, 3, 3>,
                             cudaFuncAttributeMaxDynamicSharedMemorySize, SMEM_BYTES);
        cudaFuncSetAttribute(conv_mma_kernel<3, 16, 24, 9, 9>,
                             cudaFuncAttributeMaxDynamicSharedMemorySize, SMEM_BYTES);
        smem_set = 1;
    }

    {
        dim3 grid((CC * CC * 12 + 255) / 256, 2);
        wsplit_kernel<<<grid, 256>>>(w2, w3);
    }

    conv1_lif_kernel<<<(LANES + 255) / 256, 256>>>(x, w1);

    {
        dim3 grid((N_SP + 127) / 128, BB);
        conv_mma_kernel<2, 4, 6, 3, 3><<<grid, 256, SMEM_BYTES>>>();
    }
    lif2_kernel<<<(LANES + 255) / 256, 256>>>();

    {
        dim3 grid((N_SP + 127) / 128, BB);
        conv_mma_kernel<3, 16, 24, 9, 9><<<grid, 256, SMEM_BYTES>>>();
    }
    lif3_tsum_kernel<<<(LANES + 255) / 256, 256>>>();

    {
        dim3 grid(BB, 12);
        fc_kernel<<<grid, 128>>>(wf, bf, y);
    }
}